// round 11
// baseline (speedup 1.0000x reference)
#include <cuda_runtime.h>
#include <cuda_bf16.h>
#include <cstdint>

// ============================================================================
// Problem constants
// ============================================================================
#define M_TOK 32768
#define K_IN  768
#define N_OUT 3072
#define NS    134
#define T_BLOCKS (NS * 144)

// int8 GEMM tiling: CTA 128x128, 8 warps of 64x32, BK=128 int8
#define BM 128
#define BN 128
#define BKQ 128
#define NKB (K_IN / BKQ)       // 6 k-blocks per segment
#define NSEG 3                 // q1p1, q1p2, q2p1
#define NIT (NSEG * NKB)       // 18
#define M_TILES (M_TOK / BM)   // 256
#define N_TILES (N_OUT / BN)   // 24

#define A_STAGE_BYTES (BM * BKQ)                     // 16384
#define B_STAGE_BYTES (BN * BKQ)                     // 16384
#define STAGE_BYTES (A_STAGE_BYTES + B_STAGE_BYTES)  // 32768
#define NSTAGES 3
#define SMEM_TOTAL (NSTAGES * STAGE_BYTES)           // 98304

// ============================================================================
// Device scratch (allocation-free)
// ============================================================================
__device__ float g_T[(size_t)T_BLOCKS * 128];        // 9.9 MB
__device__ float g_Wt[(size_t)N_OUT * K_IN];         // 9.4 MB, W transposed [n][k]
__device__ int8_t g_Aq1[(size_t)M_TOK * K_IN];       // 24 MB
__device__ int8_t g_Aq2[(size_t)M_TOK * K_IN];       // 24 MB
__device__ int8_t g_Bq1[(size_t)N_OUT * K_IN];       // 2.25 MB
__device__ int8_t g_Bq2[(size_t)N_OUT * K_IN];       // 2.25 MB
__device__ float g_sx[M_TOK];
__device__ float g_tw[N_OUT];

// ============================================================================
// PTX helpers (plain sm_80+ PTX only)
// ============================================================================
__device__ __forceinline__ uint32_t smem_u32(const void* p) {
    uint32_t a;
    asm("{ .reg .u64 t; cvta.to.shared.u64 t, %1; cvt.u32.u64 %0, t; }" : "=r"(a) : "l"(p));
    return a;
}

__device__ __forceinline__ void cp16(uint32_t dst, const void* src) {
    asm volatile("cp.async.cg.shared.global [%0], [%1], 16;" :: "r"(dst), "l"(src));
}
#define CP_COMMIT() asm volatile("cp.async.commit_group;" ::: "memory")
#define CP_WAIT1()  asm volatile("cp.async.wait_group 1;" ::: "memory")

#define LDMATRIX_X4(r0, r1, r2, r3, addr) \
    asm volatile("ldmatrix.sync.aligned.m8n8.x4.shared.b16 {%0,%1,%2,%3}, [%4];" \
                 : "=r"(r0), "=r"(r1), "=r"(r2), "=r"(r3) : "r"(addr))

#define MMA_S8(d, a0, a1, a2, a3, b0, b1) \
    asm volatile("mma.sync.aligned.m16n8k32.row.col.s32.s8.s8.s32 " \
                 "{%0,%1,%2,%3}, {%4,%5,%6,%7}, {%8,%9}, {%0,%1,%2,%3};" \
                 : "+r"((d)[0]), "+r"((d)[1]), "+r"((d)[2]), "+r"((d)[3]) \
                 : "r"(a0), "r"(a1), "r"(a2), "r"(a3), "r"(b0), "r"(b1))

// 128B-row swizzle: row r, 16B chunk c (0..7) -> c ^ (r & 7). Conflict-free
// for ldmatrix 8-row phases.
__device__ __forceinline__ uint32_t swz128(int r, int c) {
    return (uint32_t)(r * 128 + ((c ^ (r & 7)) << 4));
}

// ============================================================================
// Kernel 1: T[s,I,O,a,b] = sum_S W2[s,I,O,S] * W3[S,a,b]
// ============================================================================
__global__ void compute_T_kernel(const float* __restrict__ W2,
                                 const float* __restrict__ W3) {
    extern __shared__ float sW3[];
    __shared__ float sw2[8][NS];
    int blk = blockIdx.x;
    int sc  = blk / 144;
    int IO  = blk % 144;
    int t   = threadIdx.x;

    for (int j = t; j < NS * 128; j += 128) sW3[j] = W3[j];
    int s0  = sc * 8;
    int nsv = min(8, NS - s0);
    for (int j = t; j < nsv * NS; j += 128) {
        int ss = j / NS, k = j - ss * NS;
        sw2[ss][k] = W2[((size_t)(s0 + ss) * 144 + IO) * NS + k];
    }
    __syncthreads();

    for (int ss = 0; ss < nsv; ss++) {
        float acc = 0.f;
#pragma unroll 2
        for (int S = 0; S < NS; S++)
            acc += sw2[ss][S] * sW3[S * 128 + t];
        g_T[((size_t)(s0 + ss) * 144 + IO) * 128 + t] = acc;
    }
}

// ============================================================================
// Kernel 2: W transposed — g_Wt[c*768 + r] = sum_s W1[i,o,s] * T[s,I,O,a,b]
// ============================================================================
__global__ void compute_Wt_kernel(const float* __restrict__ W1) {
    int IO = blockIdx.x;
    int I = IO / 12, O = IO % 12;
    int t = threadIdx.x;
    int o = t >> 4, b = t & 15;

    __shared__ float sW1[32][128];
    __shared__ float sT[32][128];

    float acc[64];
#pragma unroll
    for (int i = 0; i < 64; i++) acc[i] = 0.f;

    for (int s0 = 0; s0 < NS; s0 += 32) {
        int ns = min(32, NS - s0);
        for (int j = t; j < ns * 128; j += 256) {
            int ss = j >> 7, io = j & 127;
            sW1[ss][io] = W1[io * NS + s0 + ss];
        }
        for (int j = t; j < ns * 128; j += 256) {
            int ss = j >> 7, ab = j & 127;
            sT[ss][ab] = g_T[((size_t)(s0 + ss) * 144 + IO) * 128 + ab];
        }
        __syncthreads();
        for (int ss = 0; ss < ns; ss++) {
            float w1v[8], tv[8];
#pragma unroll
            for (int i = 0; i < 8; i++) w1v[i] = sW1[ss][i * 16 + o];
#pragma unroll
            for (int a = 0; a < 8; a++) tv[a] = sT[ss][a * 16 + b];
#pragma unroll
            for (int i = 0; i < 8; i++)
#pragma unroll
                for (int a = 0; a < 8; a++)
                    acc[i * 8 + a] += w1v[i] * tv[a];
        }
        __syncthreads();
    }

    int c = (o * 12 + O) * 16 + b;
#pragma unroll
    for (int i = 0; i < 8; i++)
#pragma unroll
        for (int a = 0; a < 8; a++) {
            int r = (i * 12 + I) * 8 + a;
            g_Wt[(size_t)c * K_IN + r] = acc[i * 8 + a];
        }
}

// ============================================================================
// Two-digit int8 row quantizer: src row of 768 fp32 -> q1,q2 int8 + scale.
// v ~= s*(q1 + q2/128), s = rowmax/127, |q2| <= 64.  block=128, grid=rows.
// ============================================================================
__device__ __forceinline__ void quant_row(const float* __restrict__ src,
                                          int8_t* __restrict__ q1out,
                                          int8_t* __restrict__ q2out,
                                          float* __restrict__ scale_out,
                                          int row) {
    int t = threadIdx.x;
    const float* rp = src + (size_t)row * K_IN;
    float v[6];
    float mx = 0.f;
#pragma unroll
    for (int i = 0; i < 6; i++) {
        v[i] = rp[i * 128 + t];
        mx = fmaxf(mx, fabsf(v[i]));
    }
    __shared__ float wmax[4];
#pragma unroll
    for (int o = 16; o > 0; o >>= 1)
        mx = fmaxf(mx, __shfl_xor_sync(0xffffffffu, mx, o));
    if ((t & 31) == 0) wmax[t >> 5] = mx;
    __syncthreads();
    mx = fmaxf(fmaxf(wmax[0], wmax[1]), fmaxf(wmax[2], wmax[3]));
    float s = fmaxf(mx, 1e-20f) * (1.f / 127.f);
    float inv = 1.f / s;
    if (t == 0) scale_out[row] = s;
    int8_t* q1p = q1out + (size_t)row * K_IN;
    int8_t* q2p = q2out + (size_t)row * K_IN;
#pragma unroll
    for (int i = 0; i < 6; i++) {
        float f = v[i] * inv;                     // in [-127, 127]
        int a = __float2int_rn(f);
        int b = __float2int_rn((f - (float)a) * 128.f);  // in [-64, 64]
        q1p[i * 128 + t] = (int8_t)a;
        q2p[i * 128 + t] = (int8_t)b;
    }
}

__global__ void quant_x_kernel(const float* __restrict__ x) {
    quant_row(x, g_Aq1, g_Aq2, g_sx, blockIdx.x);
}
__global__ void quant_w_kernel() {
    quant_row(g_Wt, g_Bq1, g_Bq2, g_tw, blockIdx.x);
}

// ============================================================================
// Kernel 5: int8 GEMM via mma.sync m16n8k32.
// 256 threads = 8 warps (2m x 4n), warp tile 64x32, BK=128 int8, 3 stages.
// seg0: q1*p1 -> accA; seg1: q1*p2 -> accB; seg2: q2*p1 -> accB.
// y = sx*tw*(accA + accB/128) + bias.
// ============================================================================
__global__ __launch_bounds__(256, 1)
void gemm_s8_kernel(const float* __restrict__ bias, float* __restrict__ C) {
    extern __shared__ unsigned char smem[];
    const uint32_t sbase = smem_u32(smem);

    const int tid  = threadIdx.x;
    const int wid  = tid >> 5;
    const int lane = tid & 31;
    const int m0 = blockIdx.y * BM;
    const int n0 = blockIdx.x * BN;
    const int warp_m = (wid & 1) * 64;   // 0,64
    const int warp_n = (wid >> 1) * 32;  // 0,32,64,96

    int accA[4][4][4], accB[4][4][4];
#pragma unroll
    for (int i = 0; i < 4; i++)
#pragma unroll
        for (int j = 0; j < 4; j++)
#pragma unroll
            for (int q = 0; q < 4; q++) { accA[i][j][q] = 0; accB[i][j][q] = 0; }

    // ---- stage loader: A 1024 16B-chunks (4/thread), B same ----
    auto load_stage = [&](int stage, int it) {
        int seg = it / NKB;
        int k0  = (it - seg * NKB) * BKQ;
        const int8_t* As = (seg == 2) ? g_Aq2 : g_Aq1;
        const int8_t* Bs = (seg == 1) ? g_Bq2 : g_Bq1;
        uint32_t sA = sbase + stage * STAGE_BYTES;
        uint32_t sB = sA + A_STAGE_BYTES;
#pragma unroll
        for (int j = 0; j < 4; j++) {
            int id  = tid + j * 256;
            int row = id >> 3;
            int c   = id & 7;
            cp16(sA + swz128(row, c), As + (size_t)(m0 + row) * K_IN + k0 + c * 16);
        }
#pragma unroll
        for (int j = 0; j < 4; j++) {
            int id  = tid + j * 256;
            int row = id >> 3;
            int c   = id & 7;
            cp16(sB + swz128(row, c), Bs + (size_t)(n0 + row) * K_IN + k0 + c * 16);
        }
    };

    // ldmatrix addressing (computed once)
    const int a_r = warp_m + (lane & 15);          // + mt*16
    const int a_csel = lane >> 4;                  // k-half
    const int b_r = warp_n + ((lane >> 4) & 1) * 8 + (lane & 7);  // + pair*16
    const int b_csel = (lane >> 3) & 1;

    // One iteration of BK=128: 4 k32-chunks, accumulate into acc.
    auto run_iter = [&](uint32_t sA, uint32_t sB, int (&acc)[4][4][4]) {
#pragma unroll
        for (int ks = 0; ks < 4; ks++) {
            uint32_t aF[4][4];
#pragma unroll
            for (int mt = 0; mt < 4; mt++) {
                LDMATRIX_X4(aF[mt][0], aF[mt][1], aF[mt][2], aF[mt][3],
                            sA + swz128(a_r + mt * 16, ks * 2 + a_csel));
            }
            uint32_t bF[2][4];
#pragma unroll
            for (int pr = 0; pr < 2; pr++) {
                LDMATRIX_X4(bF[pr][0], bF[pr][1], bF[pr][2], bF[pr][3],
                            sB + swz128(b_r + pr * 16, ks * 2 + b_csel));
            }
#pragma unroll
            for (int mt = 0; mt < 4; mt++)
#pragma unroll
                for (int nt = 0; nt < 4; nt++) {
                    MMA_S8(acc[mt][nt],
                           aF[mt][0], aF[mt][1], aF[mt][2], aF[mt][3],
                           bF[nt >> 1][(nt & 1) * 2], bF[nt >> 1][(nt & 1) * 2 + 1]);
                }
        }
    };

    // Prologue
    load_stage(0, 0); CP_COMMIT();
    load_stage(1, 1); CP_COMMIT();

    for (int it = 0; it < NIT; it++) {
        CP_WAIT1();
        __syncthreads();
        if (it + 2 < NIT) load_stage((it + 2) % NSTAGES, it + 2);
        CP_COMMIT();

        uint32_t sA = sbase + (it % NSTAGES) * STAGE_BYTES;
        uint32_t sB = sA + A_STAGE_BYTES;
        if (it < NKB) run_iter(sA, sB, accA);
        else          run_iter(sA, sB, accB);
    }

    // ---- Epilogue: dequant + bias + store ----
    const int g = lane >> 2, tig = lane & 3;
#pragma unroll
    for (int mt = 0; mt < 4; mt++) {
        int r0 = m0 + warp_m + mt * 16 + g;
        int r1 = r0 + 8;
        float sx0 = g_sx[r0], sx1 = g_sx[r1];
#pragma unroll
        for (int nt = 0; nt < 4; nt++) {
            int col = n0 + warp_n + nt * 8 + tig * 2;
            float tw0 = g_tw[col], tw1 = g_tw[col + 1];
            float b0 = __ldg(&bias[col]), b1 = __ldg(&bias[col + 1]);
            float2 v0, v1;
            v0.x = sx0 * tw0 * ((float)accA[mt][nt][0] + (float)accB[mt][nt][0] * 0.0078125f) + b0;
            v0.y = sx0 * tw1 * ((float)accA[mt][nt][1] + (float)accB[mt][nt][1] * 0.0078125f) + b1;
            v1.x = sx1 * tw0 * ((float)accA[mt][nt][2] + (float)accB[mt][nt][2] * 0.0078125f) + b0;
            v1.y = sx1 * tw1 * ((float)accA[mt][nt][3] + (float)accB[mt][nt][3] * 0.0078125f) + b1;
            *reinterpret_cast<float2*>(&C[(size_t)r0 * N_OUT + col]) = v0;
            *reinterpret_cast<float2*>(&C[(size_t)r1 * N_OUT + col]) = v1;
        }
    }
}

// ============================================================================
// Launch. Inputs: x, W_1, W_2, W_3, b. Output fp32 (32768, 3072).
// ============================================================================
extern "C" void kernel_launch(void* const* d_in, const int* in_sizes, int n_in,
                              void* d_out, int out_size) {
    const float* x  = (const float*)d_in[0];
    const float* W1 = (const float*)d_in[1];
    const float* W2 = (const float*)d_in[2];
    const float* W3 = (const float*)d_in[3];
    const float* b  = (const float*)d_in[4];
    float* out = (float*)d_out;

    cudaFuncSetAttribute(gemm_s8_kernel,
                         cudaFuncAttributeMaxDynamicSharedMemorySize, SMEM_TOTAL);
    cudaFuncSetAttribute(compute_T_kernel,
                         cudaFuncAttributeMaxDynamicSharedMemorySize, NS * 128 * 4);

    compute_T_kernel<<<((NS + 7) / 8) * 144, 128, NS * 128 * 4>>>(W2, W3);
    compute_Wt_kernel<<<144, 256>>>(W1);
    quant_x_kernel<<<M_TOK, 128>>>(x);
    quant_w_kernel<<<N_OUT, 128>>>();
    gemm_s8_kernel<<<dim3(N_TILES, M_TILES), 256, SMEM_TOTAL>>>(b, out);
}

// round 12
// speedup vs baseline: 7.8125x; 7.8125x over previous
#include <cuda_runtime.h>
#include <cuda_fp16.h>
#include <cstdint>

// ============================================================================
// Problem constants
// ============================================================================
#define M_TOK 32768
#define K_IN  768
#define N_OUT 3072
#define NS    134
#define T_BLOCKS (NS * 144)

// GEMM tiling (single fp16 pass)
#define BM 128
#define BN 256
#define BK 64
#define NIT (K_IN / BK)        // 12 iterations
#define M_TILES (M_TOK / BM)   // 256
#define N_TILES (N_OUT / BN)   // 12

#define A_STAGE_BYTES (BM * BK * 2)      // 16384
#define B_STAGE_BYTES (BN * BK * 2)      // 32768
#define STAGE_BYTES (A_STAGE_BYTES + B_STAGE_BYTES)  // 49152
#define NSTAGES 3
#define SMEM_TOTAL (NSTAGES * STAGE_BYTES)           // 147456

// ============================================================================
// Device scratch (allocation-free)
// ============================================================================
__device__ float g_T[(size_t)T_BLOCKS * 128];      // 9.9 MB
__device__ float g_Wt[(size_t)N_OUT * K_IN];       // 9.4 MB, W transposed [n][k]
__device__ __half g_Ah[(size_t)M_TOK * K_IN];      // 48 MB
__device__ __half g_Bh[(size_t)N_OUT * K_IN];      // 4.5 MB

// ============================================================================
// PTX helpers (plain sm_80+ PTX only)
// ============================================================================
__device__ __forceinline__ uint32_t smem_u32(const void* p) {
    uint32_t a;
    asm("{ .reg .u64 t; cvta.to.shared.u64 t, %1; cvt.u32.u64 %0, t; }" : "=r"(a) : "l"(p));
    return a;
}

__device__ __forceinline__ void cp16(uint32_t dst, const void* src) {
    asm volatile("cp.async.cg.shared.global [%0], [%1], 16;" :: "r"(dst), "l"(src));
}
#define CP_COMMIT() asm volatile("cp.async.commit_group;" ::: "memory")
#define CP_WAIT1()  asm volatile("cp.async.wait_group 1;" ::: "memory")

#define LDMATRIX_X4(r0, r1, r2, r3, addr) \
    asm volatile("ldmatrix.sync.aligned.m8n8.x4.shared.b16 {%0,%1,%2,%3}, [%4];" \
                 : "=r"(r0), "=r"(r1), "=r"(r2), "=r"(r3) : "r"(addr))

#define MMA_F16(d, a0, a1, a2, a3, b0, b1) \
    asm volatile("mma.sync.aligned.m16n8k16.row.col.f32.f16.f16.f32 " \
                 "{%0,%1,%2,%3}, {%4,%5,%6,%7}, {%8,%9}, {%0,%1,%2,%3};" \
                 : "+f"((d)[0]), "+f"((d)[1]), "+f"((d)[2]), "+f"((d)[3]) \
                 : "r"(a0), "r"(a1), "r"(a2), "r"(a3), "r"(b0), "r"(b1))

// 128B-row swizzle: row r, 16B chunk c (0..7) -> c ^ (r & 7).
__device__ __forceinline__ uint32_t swz128(int r, int c) {
    return (uint32_t)(r * 128 + ((c ^ (r & 7)) << 4));
}

// ============================================================================
// Kernel 1: T[s,I,O,a,b] = sum_S W2[s,I,O,S] * W3[S,a,b]
// ============================================================================
__global__ void compute_T_kernel(const float* __restrict__ W2,
                                 const float* __restrict__ W3) {
    extern __shared__ float sW3[];
    __shared__ float sw2[8][NS];
    int blk = blockIdx.x;
    int sc  = blk / 144;
    int IO  = blk % 144;
    int t   = threadIdx.x;

    for (int j = t; j < NS * 128; j += 128) sW3[j] = W3[j];
    int s0  = sc * 8;
    int nsv = min(8, NS - s0);
    for (int j = t; j < nsv * NS; j += 128) {
        int ss = j / NS, k = j - ss * NS;
        sw2[ss][k] = W2[((size_t)(s0 + ss) * 144 + IO) * NS + k];
    }
    __syncthreads();

    for (int ss = 0; ss < nsv; ss++) {
        float acc = 0.f;
#pragma unroll 2
        for (int S = 0; S < NS; S++)
            acc += sw2[ss][S] * sW3[S * 128 + t];
        g_T[((size_t)(s0 + ss) * 144 + IO) * 128 + t] = acc;
    }
}

// ============================================================================
// Kernel 2: W transposed — g_Wt[c*768 + r] = sum_s W1[i,o,s] * T[s,I,O,a,b]
// ============================================================================
__global__ void compute_Wt_kernel(const float* __restrict__ W1) {
    int IO = blockIdx.x;
    int I = IO / 12, O = IO % 12;
    int t = threadIdx.x;
    int o = t >> 4, b = t & 15;

    __shared__ float sW1[32][128];
    __shared__ float sT[32][128];

    float acc[64];
#pragma unroll
    for (int i = 0; i < 64; i++) acc[i] = 0.f;

    for (int s0 = 0; s0 < NS; s0 += 32) {
        int ns = min(32, NS - s0);
        for (int j = t; j < ns * 128; j += 256) {
            int ss = j >> 7, io = j & 127;
            sW1[ss][io] = W1[io * NS + s0 + ss];
        }
        for (int j = t; j < ns * 128; j += 256) {
            int ss = j >> 7, ab = j & 127;
            sT[ss][ab] = g_T[((size_t)(s0 + ss) * 144 + IO) * 128 + ab];
        }
        __syncthreads();
        for (int ss = 0; ss < ns; ss++) {
            float w1v[8], tv[8];
#pragma unroll
            for (int i = 0; i < 8; i++) w1v[i] = sW1[ss][i * 16 + o];
#pragma unroll
            for (int a = 0; a < 8; a++) tv[a] = sT[ss][a * 16 + b];
#pragma unroll
            for (int i = 0; i < 8; i++)
#pragma unroll
                for (int a = 0; a < 8; a++)
                    acc[i * 8 + a] += w1v[i] * tv[a];
        }
        __syncthreads();
    }

    int c = (o * 12 + O) * 16 + b;
#pragma unroll
    for (int i = 0; i < 8; i++)
#pragma unroll
        for (int a = 0; a < 8; a++) {
            int r = (i * 12 + I) * 8 + a;
            g_Wt[(size_t)c * K_IN + r] = acc[i * 8 + a];
        }
}

// ============================================================================
// Kernel 3: x (fp32) -> fp16, row-major [M][K]
// ============================================================================
__global__ void convert_x_kernel(const float* __restrict__ x) {
    size_t gt = (size_t)blockIdx.x * blockDim.x + threadIdx.x;
    const float* xp = x + gt * 8;
    float4 v0 = *reinterpret_cast<const float4*>(xp);
    float4 v1 = *reinterpret_cast<const float4*>(xp + 4);
    float f[8] = {v0.x, v0.y, v0.z, v0.w, v1.x, v1.y, v1.z, v1.w};
    uint32_t hw[4];
#pragma unroll
    for (int j = 0; j < 4; j++) {
        __half2 h = __floats2half2_rn(f[2*j], f[2*j+1]);
        hw[j] = *reinterpret_cast<uint32_t*>(&h);
    }
    *reinterpret_cast<uint4*>(&g_Ah[gt * 8]) = make_uint4(hw[0], hw[1], hw[2], hw[3]);
}

// ============================================================================
// Kernel 4: g_Wt (fp32 [n][k]) -> fp16 [n][k]
// ============================================================================
__global__ void convert_W_kernel() {
    size_t gt = (size_t)blockIdx.x * blockDim.x + threadIdx.x;
    const float* wp = g_Wt + gt * 8;
    float4 v0 = *reinterpret_cast<const float4*>(wp);
    float4 v1 = *reinterpret_cast<const float4*>(wp + 4);
    float f[8] = {v0.x, v0.y, v0.z, v0.w, v1.x, v1.y, v1.z, v1.w};
    uint32_t hw[4];
#pragma unroll
    for (int j = 0; j < 4; j++) {
        __half2 h = __floats2half2_rn(f[2*j], f[2*j+1]);
        hw[j] = *reinterpret_cast<uint32_t*>(&h);
    }
    *reinterpret_cast<uint4*>(&g_Bh[gt * 8]) = make_uint4(hw[0], hw[1], hw[2], hw[3]);
}

// ============================================================================
// Kernel 5: GEMM via mma.sync fp16 (fp32 accum). 256 threads = 8 warps
// (2m x 4n), warp tile 64x64, BK=64, 3-stage cp.async, double-buffered frags.
// ============================================================================
__global__ __launch_bounds__(256, 1)
void gemm_mma_kernel(const float* __restrict__ bias, float* __restrict__ C) {
    extern __shared__ unsigned char smem[];
    const uint32_t sbase = smem_u32(smem);

    const int tid  = threadIdx.x;
    const int wid  = tid >> 5;
    const int lane = tid & 31;
    const int m0 = blockIdx.y * BM;
    const int n0 = blockIdx.x * BN;
    const int warp_m = (wid & 1) * 64;   // 0,64
    const int warp_n = (wid >> 1) * 64;  // 0,64,128,192

    float acc[4][8][4];
#pragma unroll
    for (int i = 0; i < 4; i++)
#pragma unroll
        for (int j = 0; j < 8; j++)
#pragma unroll
            for (int q = 0; q < 4; q++) acc[i][j][q] = 0.f;

    // ---- stage loader: A 1024 chunks (4/thread), B 2048 chunks (8/thread) ----
    auto load_stage = [&](int stage, int it) {
        int k0 = it * BK;
        uint32_t sA = sbase + stage * STAGE_BYTES;
        uint32_t sB = sA + A_STAGE_BYTES;
#pragma unroll
        for (int j = 0; j < 4; j++) {
            int id  = tid + j * 256;
            int row = id >> 3;
            int c   = id & 7;
            cp16(sA + swz128(row, c), g_Ah + (size_t)(m0 + row) * K_IN + k0 + c * 8);
        }
#pragma unroll
        for (int j = 0; j < 8; j++) {
            int id  = tid + j * 256;
            int row = id >> 3;
            int c   = id & 7;
            cp16(sB + swz128(row, c), g_Bh + (size_t)(n0 + row) * K_IN + k0 + c * 8);
        }
    };

    // Fragment double buffers
    uint32_t aF[2][4][4], bF[2][4][4];
    const int fr = lane & 15;
    const int fc = lane >> 4;

    auto load_frags = [&](uint32_t sA, uint32_t sB, int ks, int buf) {
#pragma unroll
        for (int mt = 0; mt < 4; mt++) {
            int r = warp_m + mt * 16 + fr;
            LDMATRIX_X4(aF[buf][mt][0], aF[buf][mt][1], aF[buf][mt][2], aF[buf][mt][3],
                        sA + swz128(r, ks * 2 + fc));
        }
#pragma unroll
        for (int nt = 0; nt < 4; nt++) {
            int r = warp_n + nt * 16 + fr;
            LDMATRIX_X4(bF[buf][nt][0], bF[buf][nt][1], bF[buf][nt][2], bF[buf][nt][3],
                        sB + swz128(r, ks * 2 + fc));
        }
    };

    auto do_mma = [&](int buf) {
#pragma unroll
        for (int mt = 0; mt < 4; mt++)
#pragma unroll
            for (int nt = 0; nt < 4; nt++)
#pragma unroll
                for (int p = 0; p < 2; p++) {
                    MMA_F16(acc[mt][nt * 2 + p],
                            aF[buf][mt][0], aF[buf][mt][1], aF[buf][mt][2], aF[buf][mt][3],
                            bF[buf][nt][p], bF[buf][nt][2 + p]);
                }
    };

    // Prologue: stages 0 and 1
    load_stage(0, 0); CP_COMMIT();
    load_stage(1, 1); CP_COMMIT();

    for (int it = 0; it < NIT; it++) {
        CP_WAIT1();               // stage it%3 resident
        __syncthreads();          // all warps done with stage (it+2)%3's old data
        if (it + 2 < NIT) load_stage((it + 2) % NSTAGES, it + 2);
        CP_COMMIT();

        uint32_t sA = sbase + (it % NSTAGES) * STAGE_BYTES;
        uint32_t sB = sA + A_STAGE_BYTES;

        load_frags(sA, sB, 0, 0);
#pragma unroll
        for (int ks = 0; ks < 4; ks++) {
            if (ks < 3) load_frags(sA, sB, ks + 1, (ks + 1) & 1);
            do_mma(ks & 1);
        }
    }

    // ---- Epilogue: bias + store ----
    const int g = lane >> 2, tig = lane & 3;
    float bv[8][2];
#pragma unroll
    for (int nn = 0; nn < 8; nn++) {
        int col = n0 + warp_n + nn * 8 + tig * 2;
        bv[nn][0] = __ldg(&bias[col]);
        bv[nn][1] = __ldg(&bias[col + 1]);
    }
#pragma unroll
    for (int mt = 0; mt < 4; mt++) {
        int r0 = m0 + warp_m + mt * 16 + g;
        int r1 = r0 + 8;
#pragma unroll
        for (int nn = 0; nn < 8; nn++) {
            int col = n0 + warp_n + nn * 8 + tig * 2;
            float2 v0 = make_float2(acc[mt][nn][0] + bv[nn][0], acc[mt][nn][1] + bv[nn][1]);
            float2 v1 = make_float2(acc[mt][nn][2] + bv[nn][0], acc[mt][nn][3] + bv[nn][1]);
            *reinterpret_cast<float2*>(&C[(size_t)r0 * N_OUT + col]) = v0;
            *reinterpret_cast<float2*>(&C[(size_t)r1 * N_OUT + col]) = v1;
        }
    }
}

// ============================================================================
// Launch. Inputs: x, W_1, W_2, W_3, b. Output fp32 (32768, 3072).
// ============================================================================
extern "C" void kernel_launch(void* const* d_in, const int* in_sizes, int n_in,
                              void* d_out, int out_size) {
    const float* x  = (const float*)d_in[0];
    const float* W1 = (const float*)d_in[1];
    const float* W2 = (const float*)d_in[2];
    const float* W3 = (const float*)d_in[3];
    const float* b  = (const float*)d_in[4];
    float* out = (float*)d_out;

    cudaFuncSetAttribute(gemm_mma_kernel,
                         cudaFuncAttributeMaxDynamicSharedMemorySize, SMEM_TOTAL);
    cudaFuncSetAttribute(compute_T_kernel,
                         cudaFuncAttributeMaxDynamicSharedMemorySize, NS * 128 * 4);

    compute_T_kernel<<<((NS + 7) / 8) * 144, 128, NS * 128 * 4>>>(W2, W3);
    compute_Wt_kernel<<<144, 256>>>(W1);
    convert_x_kernel<<<(M_TOK * 96) / 256, 256>>>(x);
    convert_W_kernel<<<(N_OUT * 96) / 256, 256>>>();
    gemm_mma_kernel<<<dim3(N_TILES, M_TILES), 256, SMEM_TOTAL>>>(b, out);
}

// round 13
// speedup vs baseline: 8.3770x; 1.0723x over previous
#include <cuda_runtime.h>
#include <cuda_fp16.h>
#include <cstdint>

// ============================================================================
// Problem constants
// ============================================================================
#define M_TOK 32768
#define K_IN  768
#define N_OUT 3072
#define NS    134
#define T_BLOCKS (NS * 144)

// GEMM tiling (single fp16 pass, 2 CTAs/SM)
#define BM 128
#define BN 128
#define BK 64
#define NIT (K_IN / BK)        // 12 iterations
#define M_TILES (M_TOK / BM)   // 256
#define N_TILES (N_OUT / BN)   // 24

#define A_STAGE_BYTES (BM * BK * 2)      // 16384
#define B_STAGE_BYTES (BN * BK * 2)      // 16384
#define STAGE_BYTES (A_STAGE_BYTES + B_STAGE_BYTES)  // 32768
#define NSTAGES 2
#define SMEM_TOTAL (NSTAGES * STAGE_BYTES)           // 65536

// ============================================================================
// Device scratch (allocation-free)
// ============================================================================
__device__ float g_T[(size_t)T_BLOCKS * 128];      // 9.9 MB
__device__ __half g_Ah[(size_t)M_TOK * K_IN];      // 48 MB
__device__ __half g_Bh[(size_t)N_OUT * K_IN];      // 4.5 MB  (W^T as fp16, [n][k])

// ============================================================================
// PTX helpers (plain sm_80+ PTX only)
// ============================================================================
__device__ __forceinline__ uint32_t smem_u32(const void* p) {
    uint32_t a;
    asm("{ .reg .u64 t; cvta.to.shared.u64 t, %1; cvt.u32.u64 %0, t; }" : "=r"(a) : "l"(p));
    return a;
}

__device__ __forceinline__ void cp16(uint32_t dst, const void* src) {
    asm volatile("cp.async.cg.shared.global [%0], [%1], 16;" :: "r"(dst), "l"(src));
}
#define CP_COMMIT() asm volatile("cp.async.commit_group;" ::: "memory")
#define CP_WAIT1()  asm volatile("cp.async.wait_group 1;" ::: "memory")

#define LDMATRIX_X4(r0, r1, r2, r3, addr) \
    asm volatile("ldmatrix.sync.aligned.m8n8.x4.shared.b16 {%0,%1,%2,%3}, [%4];" \
                 : "=r"(r0), "=r"(r1), "=r"(r2), "=r"(r3) : "r"(addr))

#define MMA_F16(d, a0, a1, a2, a3, b0, b1) \
    asm volatile("mma.sync.aligned.m16n8k16.row.col.f32.f16.f16.f32 " \
                 "{%0,%1,%2,%3}, {%4,%5,%6,%7}, {%8,%9}, {%0,%1,%2,%3};" \
                 : "+f"((d)[0]), "+f"((d)[1]), "+f"((d)[2]), "+f"((d)[3]) \
                 : "r"(a0), "r"(a1), "r"(a2), "r"(a3), "r"(b0), "r"(b1))

// 128B-row swizzle: row r, 16B chunk c (0..7) -> c ^ (r & 7).
__device__ __forceinline__ uint32_t swz128(int r, int c) {
    return (uint32_t)(r * 128 + ((c ^ (r & 7)) << 4));
}

// ============================================================================
// Kernel 1: T[s,I,O,a,b] = sum_S W2[s,I,O,S] * W3[S,a,b]
// ============================================================================
__global__ void compute_T_kernel(const float* __restrict__ W2,
                                 const float* __restrict__ W3) {
    extern __shared__ float sW3[];
    __shared__ float sw2[8][NS];
    int blk = blockIdx.x;
    int sc  = blk / 144;
    int IO  = blk % 144;
    int t   = threadIdx.x;

    for (int j = t; j < NS * 128; j += 128) sW3[j] = W3[j];
    int s0  = sc * 8;
    int nsv = min(8, NS - s0);
    for (int j = t; j < nsv * NS; j += 128) {
        int ss = j / NS, k = j - ss * NS;
        sw2[ss][k] = W2[((size_t)(s0 + ss) * 144 + IO) * NS + k];
    }
    __syncthreads();

    for (int ss = 0; ss < nsv; ss++) {
        float acc = 0.f;
#pragma unroll 2
        for (int S = 0; S < NS; S++)
            acc += sw2[ss][S] * sW3[S * 128 + t];
        g_T[((size_t)(s0 + ss) * 144 + IO) * 128 + t] = acc;
    }
}

// ============================================================================
// Kernel 2 (fused): W^T directly to fp16 — g_Bh[c*768 + r] = fp16(sum_s ...)
//           r=(i*12+I)*8+a, c=(o*12+O)*16+b
// ============================================================================
__global__ void compute_Wt_kernel(const float* __restrict__ W1) {
    int IO = blockIdx.x;
    int I = IO / 12, O = IO % 12;
    int t = threadIdx.x;
    int o = t >> 4, b = t & 15;

    __shared__ float sW1[32][128];
    __shared__ float sT[32][128];

    float acc[64];
#pragma unroll
    for (int i = 0; i < 64; i++) acc[i] = 0.f;

    for (int s0 = 0; s0 < NS; s0 += 32) {
        int ns = min(32, NS - s0);
        for (int j = t; j < ns * 128; j += 256) {
            int ss = j >> 7, io = j & 127;
            sW1[ss][io] = W1[io * NS + s0 + ss];
        }
        for (int j = t; j < ns * 128; j += 256) {
            int ss = j >> 7, ab = j & 127;
            sT[ss][ab] = g_T[((size_t)(s0 + ss) * 144 + IO) * 128 + ab];
        }
        __syncthreads();
        for (int ss = 0; ss < ns; ss++) {
            float w1v[8], tv[8];
#pragma unroll
            for (int i = 0; i < 8; i++) w1v[i] = sW1[ss][i * 16 + o];
#pragma unroll
            for (int a = 0; a < 8; a++) tv[a] = sT[ss][a * 16 + b];
#pragma unroll
            for (int i = 0; i < 8; i++)
#pragma unroll
                for (int a = 0; a < 8; a++)
                    acc[i * 8 + a] += w1v[i] * tv[a];
        }
        __syncthreads();
    }

    int c = (o * 12 + O) * 16 + b;
#pragma unroll
    for (int i = 0; i < 8; i++)
#pragma unroll
        for (int a = 0; a < 8; a++) {
            int r = (i * 12 + I) * 8 + a;
            g_Bh[(size_t)c * K_IN + r] = __float2half_rn(acc[i * 8 + a]);
        }
}

// ============================================================================
// Kernel 3: x (fp32) -> fp16, row-major [M][K]
// ============================================================================
__global__ void convert_x_kernel(const float* __restrict__ x) {
    size_t gt = (size_t)blockIdx.x * blockDim.x + threadIdx.x;
    const float* xp = x + gt * 8;
    float4 v0 = *reinterpret_cast<const float4*>(xp);
    float4 v1 = *reinterpret_cast<const float4*>(xp + 4);
    float f[8] = {v0.x, v0.y, v0.z, v0.w, v1.x, v1.y, v1.z, v1.w};
    uint32_t hw[4];
#pragma unroll
    for (int j = 0; j < 4; j++) {
        __half2 h = __floats2half2_rn(f[2*j], f[2*j+1]);
        hw[j] = *reinterpret_cast<uint32_t*>(&h);
    }
    *reinterpret_cast<uint4*>(&g_Ah[gt * 8]) = make_uint4(hw[0], hw[1], hw[2], hw[3]);
}

// ============================================================================
// Kernel 4: GEMM via mma.sync fp16 (fp32 accum). 256 threads = 8 warps
// (2m x 4n), warp tile 64x32, BK=64, 2-stage cp.async, 2 CTAs/SM.
// ============================================================================
__global__ __launch_bounds__(256, 2)
void gemm_mma_kernel(const float* __restrict__ bias, float* __restrict__ C) {
    extern __shared__ unsigned char smem[];
    const uint32_t sbase = smem_u32(smem);

    const int tid  = threadIdx.x;
    const int wid  = tid >> 5;
    const int lane = tid & 31;
    const int m0 = blockIdx.y * BM;
    const int n0 = blockIdx.x * BN;
    const int warp_m = (wid & 1) * 64;   // 0,64
    const int warp_n = (wid >> 1) * 32;  // 0,32,64,96

    float acc[4][4][4];
#pragma unroll
    for (int i = 0; i < 4; i++)
#pragma unroll
        for (int j = 0; j < 4; j++)
#pragma unroll
            for (int q = 0; q < 4; q++) acc[i][j][q] = 0.f;

    // ---- stage loader: A 1024 chunks (4/thread), B 1024 chunks (4/thread) ----
    auto load_stage = [&](int stage, int it) {
        int k0 = it * BK;
        uint32_t sA = sbase + stage * STAGE_BYTES;
        uint32_t sB = sA + A_STAGE_BYTES;
#pragma unroll
        for (int j = 0; j < 4; j++) {
            int id  = tid + j * 256;
            int row = id >> 3;
            int c   = id & 7;
            cp16(sA + swz128(row, c), g_Ah + (size_t)(m0 + row) * K_IN + k0 + c * 8);
        }
#pragma unroll
        for (int j = 0; j < 4; j++) {
            int id  = tid + j * 256;
            int row = id >> 3;
            int c   = id & 7;
            cp16(sB + swz128(row, c), g_Bh + (size_t)(n0 + row) * K_IN + k0 + c * 8);
        }
    };

    const int fr = lane & 15;
    const int fc = lane >> 4;

    // Prologue: stage 0
    load_stage(0, 0); CP_COMMIT();

    for (int it = 0; it < NIT; it++) {
        __syncthreads();           // all warps done computing iter it-1 (buffer (it+1)&1)
        if (it + 1 < NIT) load_stage((it + 1) & 1, it + 1);
        CP_COMMIT();
        CP_WAIT1();                // stage it&1 landed (lookahead group may fly)
        __syncthreads();           // cross-thread visibility of stage it&1

        uint32_t sA = sbase + (it & 1) * STAGE_BYTES;
        uint32_t sB = sA + A_STAGE_BYTES;

#pragma unroll
        for (int ks = 0; ks < 4; ks++) {
            uint32_t aF[4][4];
#pragma unroll
            for (int mt = 0; mt < 4; mt++) {
                int r = warp_m + mt * 16 + fr;
                LDMATRIX_X4(aF[mt][0], aF[mt][1], aF[mt][2], aF[mt][3],
                            sA + swz128(r, ks * 2 + fc));
            }
            uint32_t bF[2][4];
#pragma unroll
            for (int nt = 0; nt < 2; nt++) {
                int r = warp_n + nt * 16 + fr;
                LDMATRIX_X4(bF[nt][0], bF[nt][1], bF[nt][2], bF[nt][3],
                            sB + swz128(r, ks * 2 + fc));
            }
#pragma unroll
            for (int mt = 0; mt < 4; mt++)
#pragma unroll
                for (int nt = 0; nt < 2; nt++)
#pragma unroll
                    for (int p = 0; p < 2; p++) {
                        MMA_F16(acc[mt][nt * 2 + p],
                                aF[mt][0], aF[mt][1], aF[mt][2], aF[mt][3],
                                bF[nt][p], bF[nt][2 + p]);
                    }
        }
    }

    // ---- Epilogue: bias + store ----
    const int g = lane >> 2, tig = lane & 3;
    float bv[4][2];
#pragma unroll
    for (int nn = 0; nn < 4; nn++) {
        int col = n0 + warp_n + nn * 8 + tig * 2;
        bv[nn][0] = __ldg(&bias[col]);
        bv[nn][1] = __ldg(&bias[col + 1]);
    }
#pragma unroll
    for (int mt = 0; mt < 4; mt++) {
        int r0 = m0 + warp_m + mt * 16 + g;
        int r1 = r0 + 8;
#pragma unroll
        for (int nn = 0; nn < 4; nn++) {
            int col = n0 + warp_n + nn * 8 + tig * 2;
            float2 v0 = make_float2(acc[mt][nn][0] + bv[nn][0], acc[mt][nn][1] + bv[nn][1]);
            float2 v1 = make_float2(acc[mt][nn][2] + bv[nn][0], acc[mt][nn][3] + bv[nn][1]);
            *reinterpret_cast<float2*>(&C[(size_t)r0 * N_OUT + col]) = v0;
            *reinterpret_cast<float2*>(&C[(size_t)r1 * N_OUT + col]) = v1;
        }
    }
}

// ============================================================================
// Launch. Inputs: x, W_1, W_2, W_3, b. Output fp32 (32768, 3072).
// ============================================================================
extern "C" void kernel_launch(void* const* d_in, const int* in_sizes, int n_in,
                              void* d_out, int out_size) {
    const float* x  = (const float*)d_in[0];
    const float* W1 = (const float*)d_in[1];
    const float* W2 = (const float*)d_in[2];
    const float* W3 = (const float*)d_in[3];
    const float* b  = (const float*)d_in[4];
    float* out = (float*)d_out;

    cudaFuncSetAttribute(gemm_mma_kernel,
                         cudaFuncAttributeMaxDynamicSharedMemorySize, SMEM_TOTAL);
    cudaFuncSetAttribute(compute_T_kernel,
                         cudaFuncAttributeMaxDynamicSharedMemorySize, NS * 128 * 4);

    compute_T_kernel<<<((NS + 7) / 8) * 144, 128, NS * 128 * 4>>>(W2, W3);
    compute_Wt_kernel<<<144, 256>>>(W1);
    convert_x_kernel<<<(M_TOK * 96) / 256, 256>>>(x);
    gemm_mma_kernel<<<dim3(N_TILES, M_TILES), 256, SMEM_TOTAL>>>(b, out);
}